// round 2
// baseline (speedup 1.0000x reference)
#include <cuda_runtime.h>

#define N_ATOMS 50000
#define IN_DIM 128
#define HID 256
#define N_ELEM 4
#define N_IMG 500
#define TB 32            // atoms per MLP block
#define MLP_THREADS 256

// ---------------- device scratch (static allocs only) ----------------
__device__ float d_g[N_ATOMS * IN_DIM];            // dE/dfp, 25.6 MB (L2-resident)
__device__ float d_W0T[N_ELEM * HID * IN_DIM];     // W0^T  [e][h][d]
__device__ float d_W1T[N_ELEM * HID * HID];        // W1^T  [e][j][i]
__device__ int   d_perm[N_ATOMS];                  // atoms grouped by element
__device__ int   d_offsets[N_ELEM];
__device__ int   d_counts[N_ELEM];
__device__ int   d_cursor[N_ELEM];

__device__ __forceinline__ int elem_of(int z) {
    return (z == 1) ? 0 : (z == 6) ? 1 : (z == 8) ? 2 : 3;
}

// ---------------- misc kernels ----------------
__global__ void zero_kernel(float* __restrict__ out, int n) {
    int i = blockIdx.x * blockDim.x + threadIdx.x;
    if (i < n) out[i] = 0.0f;
}

__global__ void count_kernel(const int* __restrict__ z, int n) {
    __shared__ int c[N_ELEM];
    int tid = threadIdx.x;
    if (tid < N_ELEM) c[tid] = 0;
    __syncthreads();
    for (int i = tid; i < n; i += blockDim.x)
        atomicAdd(&c[elem_of(z[i])], 1);
    __syncthreads();
    if (tid == 0) {
        int off = 0;
        for (int e = 0; e < N_ELEM; e++) {
            d_offsets[e] = off;
            d_counts[e]  = c[e];
            d_cursor[e]  = off;
            off += c[e];
        }
    }
}

__global__ void scatter_kernel(const int* __restrict__ z, int n) {
    int a = blockIdx.x * blockDim.x + threadIdx.x;
    bool valid = a < n;
    int myE = valid ? elem_of(z[a]) : -1;
    int lane = threadIdx.x & 31;
    #pragma unroll
    for (int e = 0; e < N_ELEM; e++) {
        unsigned m = __ballot_sync(0xffffffffu, myE == e);
        if (!m) continue;
        int leader = __ffs(m) - 1;
        int base = 0;
        if (lane == leader) base = atomicAdd(&d_cursor[e], __popc(m));
        base = __shfl_sync(0xffffffffu, base, leader);
        if (myE == e) {
            int rank = __popc(m & ((1u << lane) - 1u));
            d_perm[base + rank] = a;
        }
    }
}

__global__ void transpose_kernel(const float* __restrict__ W0,
                                 const float* __restrict__ W1) {
    int i = blockIdx.x * blockDim.x + threadIdx.x;
    const int n0 = N_ELEM * IN_DIM * HID;
    const int n1 = N_ELEM * HID * HID;
    if (i < n0) {
        int e = i / (IN_DIM * HID);
        int r = i % (IN_DIM * HID);
        int d = r / HID, h = r % HID;
        d_W0T[e * (HID * IN_DIM) + h * IN_DIM + d] = W0[i];
    }
    if (i < n1) {
        int e = i / (HID * HID);
        int r = i % (HID * HID);
        int ii = r / HID, jj = r % HID;
        d_W1T[e * (HID * HID) + jj * HID + ii] = W1[i];
    }
}

// ---------------- fused per-element MLP fwd + bwd ----------------
// Block: 32 atoms of one element, 256 threads.
// Thread tiling: ag = tid>>5 -> 4 atoms (a0=4*ag), jg = tid&31 -> 8 outputs (j0=8*jg).
__global__ void mlp_kernel(const float* __restrict__ fp,
                           const int*   __restrict__ image_idx,
                           const float* __restrict__ W0, const float* __restrict__ b0,
                           const float* __restrict__ W1, const float* __restrict__ b1,
                           const float* __restrict__ W2, const float* __restrict__ b2,
                           float* __restrict__ out_energy)
{
    const int e = blockIdx.y;
    const int cnt = d_counts[e];
    const int start = blockIdx.x * TB;
    if (start >= cnt) return;
    const int off = d_offsets[e];
    const int na  = min(TB, cnt - start);

    extern __shared__ float sm[];
    float* fp_s  = sm;                  // [TB][IN_DIM]   4096 f
    float* h0_s  = sm + 4096;           // [TB][HID]      8192 f  (later holds dh0)
    float* dh1_s = sm + 4096 + 8192;    // [TB][HID]      8192 f
    float* o_s   = sm + 4096 + 16384;   // [TB]
    int*   aidx  = (int*)(o_s + TB);    // [TB]

    const int tid = threadIdx.x;
    if (tid < TB) {
        int a = d_perm[off + start + ((tid < na) ? tid : 0)];
        aidx[tid] = a;
        o_s[tid]  = 0.0f;
    }
    __syncthreads();

    // load fingerprint tile (coalesced)
    for (int l = tid; l < TB * IN_DIM; l += MLP_THREADS) {
        int a = l >> 7, d = l & (IN_DIM - 1);
        fp_s[l] = fp[aidx[a] * IN_DIM + d];
    }
    __syncthreads();

    const int ag = tid >> 5, jg = tid & 31;
    const int a0 = ag * 4,  j0 = jg * 8;

    const float* W0e  = W0 + e * (IN_DIM * HID);
    const float* W1e  = W1 + e * (HID * HID);
    const float* W0Te = d_W0T + e * (HID * IN_DIM);
    const float* W1Te = d_W1T + e * (HID * HID);

    // ---- layer 0: h0 = tanh(fp @ W0 + b0) ----
    float acc[4][8];
    {
        float4 bA = *(const float4*)&b0[e * HID + j0];
        float4 bB = *(const float4*)&b0[e * HID + j0 + 4];
        #pragma unroll
        for (int ia = 0; ia < 4; ia++) {
            acc[ia][0]=bA.x; acc[ia][1]=bA.y; acc[ia][2]=bA.z; acc[ia][3]=bA.w;
            acc[ia][4]=bB.x; acc[ia][5]=bB.y; acc[ia][6]=bB.z; acc[ia][7]=bB.w;
        }
    }
    #pragma unroll 4
    for (int d = 0; d < IN_DIM; d++) {
        float4 wA = *(const float4*)&W0e[d * HID + j0];
        float4 wB = *(const float4*)&W0e[d * HID + j0 + 4];
        float w[8] = {wA.x,wA.y,wA.z,wA.w,wB.x,wB.y,wB.z,wB.w};
        float fv[4];
        #pragma unroll
        for (int ia = 0; ia < 4; ia++) fv[ia] = fp_s[(a0 + ia) * IN_DIM + d];
        #pragma unroll
        for (int ia = 0; ia < 4; ia++)
            #pragma unroll
            for (int j = 0; j < 8; j++) acc[ia][j] += fv[ia] * w[j];
    }
    #pragma unroll
    for (int ia = 0; ia < 4; ia++) {
        float h[8];
        #pragma unroll
        for (int j = 0; j < 8; j++) h[j] = tanhf(acc[ia][j]);
        *(float4*)&h0_s[(a0 + ia) * HID + j0]     = make_float4(h[0],h[1],h[2],h[3]);
        *(float4*)&h0_s[(a0 + ia) * HID + j0 + 4] = make_float4(h[4],h[5],h[6],h[7]);
    }
    __syncthreads();

    // ---- layer 1: h1 = tanh(h0 @ W1 + b1); o += h1.W2; dh1 = W2*(1-h1^2) ----
    {
        float4 bA = *(const float4*)&b1[e * HID + j0];
        float4 bB = *(const float4*)&b1[e * HID + j0 + 4];
        #pragma unroll
        for (int ia = 0; ia < 4; ia++) {
            acc[ia][0]=bA.x; acc[ia][1]=bA.y; acc[ia][2]=bA.z; acc[ia][3]=bA.w;
            acc[ia][4]=bB.x; acc[ia][5]=bB.y; acc[ia][6]=bB.z; acc[ia][7]=bB.w;
        }
    }
    #pragma unroll 4
    for (int i = 0; i < HID; i++) {
        float4 wA = *(const float4*)&W1e[i * HID + j0];
        float4 wB = *(const float4*)&W1e[i * HID + j0 + 4];
        float w[8] = {wA.x,wA.y,wA.z,wA.w,wB.x,wB.y,wB.z,wB.w};
        float fv[4];
        #pragma unroll
        for (int ia = 0; ia < 4; ia++) fv[ia] = h0_s[(a0 + ia) * HID + i];
        #pragma unroll
        for (int ia = 0; ia < 4; ia++)
            #pragma unroll
            for (int j = 0; j < 8; j++) acc[ia][j] += fv[ia] * w[j];
    }
    {
        float4 wA = *(const float4*)&W2[e * HID + j0];
        float4 wB = *(const float4*)&W2[e * HID + j0 + 4];
        float w2r[8] = {wA.x,wA.y,wA.z,wA.w,wB.x,wB.y,wB.z,wB.w};
        #pragma unroll
        for (int ia = 0; ia < 4; ia++) {
            float opart = 0.0f;
            float dh[8];
            #pragma unroll
            for (int j = 0; j < 8; j++) {
                float h1 = tanhf(acc[ia][j]);
                opart += h1 * w2r[j];
                dh[j] = w2r[j] * (1.0f - h1 * h1);
            }
            *(float4*)&dh1_s[(a0 + ia) * HID + j0]     = make_float4(dh[0],dh[1],dh[2],dh[3]);
            *(float4*)&dh1_s[(a0 + ia) * HID + j0 + 4] = make_float4(dh[4],dh[5],dh[6],dh[7]);
            atomicAdd(&o_s[a0 + ia], opart);
        }
    }
    __syncthreads();

    // ---- bwd layer1: dh0 = (1-h0^2) * (dh1 @ W1^T)  (written in-place into h0_s) ----
    const int i0 = jg * 8;
    #pragma unroll
    for (int ia = 0; ia < 4; ia++)
        #pragma unroll
        for (int j = 0; j < 8; j++) acc[ia][j] = 0.0f;
    #pragma unroll 4
    for (int j = 0; j < HID; j++) {
        float4 wA = *(const float4*)&W1Te[j * HID + i0];
        float4 wB = *(const float4*)&W1Te[j * HID + i0 + 4];
        float w[8] = {wA.x,wA.y,wA.z,wA.w,wB.x,wB.y,wB.z,wB.w};
        float fv[4];
        #pragma unroll
        for (int ia = 0; ia < 4; ia++) fv[ia] = dh1_s[(a0 + ia) * HID + j];
        #pragma unroll
        for (int ia = 0; ia < 4; ia++)
            #pragma unroll
            for (int jj = 0; jj < 8; jj++) acc[ia][jj] += fv[ia] * w[jj];
    }
    #pragma unroll
    for (int ia = 0; ia < 4; ia++) {
        float v[8];
        #pragma unroll
        for (int jj = 0; jj < 8; jj++) {
            float h0v = h0_s[(a0 + ia) * HID + i0 + jj];
            v[jj] = (1.0f - h0v * h0v) * acc[ia][jj];
        }
        *(float4*)&h0_s[(a0 + ia) * HID + i0]     = make_float4(v[0],v[1],v[2],v[3]);
        *(float4*)&h0_s[(a0 + ia) * HID + i0 + 4] = make_float4(v[4],v[5],v[6],v[7]);
    }
    __syncthreads();

    // ---- bwd layer0: g = dh0 @ W0^T  -> d_g[atom][d] ----
    const int d0 = jg * 4;
    float accg[4][4];
    #pragma unroll
    for (int ia = 0; ia < 4; ia++)
        #pragma unroll
        for (int j = 0; j < 4; j++) accg[ia][j] = 0.0f;
    #pragma unroll 4
    for (int i = 0; i < HID; i++) {
        float4 w = *(const float4*)&W0Te[i * IN_DIM + d0];
        float fv[4];
        #pragma unroll
        for (int ia = 0; ia < 4; ia++) fv[ia] = h0_s[(a0 + ia) * HID + i];  // dh0
        #pragma unroll
        for (int ia = 0; ia < 4; ia++) {
            accg[ia][0] += fv[ia] * w.x;
            accg[ia][1] += fv[ia] * w.y;
            accg[ia][2] += fv[ia] * w.z;
            accg[ia][3] += fv[ia] * w.w;
        }
    }
    #pragma unroll
    for (int ia = 0; ia < 4; ia++) {
        int a = a0 + ia;
        if (a < na) {
            *(float4*)&d_g[aidx[a] * IN_DIM + d0] =
                make_float4(accg[ia][0], accg[ia][1], accg[ia][2], accg[ia][3]);
        }
    }

    // ---- energy: atomic segment-sum over images ----
    if (tid < na) {
        float o = o_s[tid] + b2[e];
        atomicAdd(&out_energy[image_idx[aidx[tid]]], o);
    }
}

// ---------------- sparse force scatter: forces = -fprimes^T @ g ----------------
__global__ void force_kernel(const int* __restrict__ rows,
                             const int* __restrict__ cols,
                             const float* __restrict__ vals,
                             int nnz, float* __restrict__ forces) {
    int i = blockIdx.x * blockDim.x + threadIdx.x;
    int stride = gridDim.x * blockDim.x;
    for (; i < nnz; i += stride) {
        float contrib = -vals[i] * d_g[rows[i]];
        atomicAdd(&forces[cols[i]], contrib);
    }
}

// ---------------- launch ----------------
extern "C" void kernel_launch(void* const* d_in, const int* in_sizes, int n_in,
                              void* d_out, int out_size) {
    const float* fingerprints = (const float*)d_in[0];
    const int*   atomic_num   = (const int*)  d_in[1];
    const int*   image_idx    = (const int*)  d_in[2];
    const int*   fprime_rows  = (const int*)  d_in[3];
    const int*   fprime_cols  = (const int*)  d_in[4];
    const float* fprime_vals  = (const float*)d_in[5];
    const float* W0 = (const float*)d_in[6];
    const float* b0 = (const float*)d_in[7];
    const float* W1 = (const float*)d_in[8];
    const float* b1 = (const float*)d_in[9];
    const float* W2 = (const float*)d_in[10];
    const float* b2 = (const float*)d_in[11];
    float* out = (float*)d_out;                 // [0,500): energy, [500,150500): forces
    const int nnz = in_sizes[3];

    // out = zeros (out is poisoned; atomics accumulate into it)
    zero_kernel<<<(out_size + 255) / 256, 256>>>(out, out_size);

    // bucket atoms by element
    count_kernel<<<1, 1024>>>(atomic_num, N_ATOMS);
    scatter_kernel<<<(N_ATOMS + 255) / 256, 256>>>(atomic_num, N_ATOMS);

    // weight transposes for coalesced backward GEMMs
    transpose_kernel<<<(N_ELEM * HID * HID + 255) / 256, 256>>>(W0, W1);

    // fused MLP fwd+bwd
    const int smem_bytes = (4096 + 8192 + 8192 + TB) * 4 + TB * 4;
    cudaFuncSetAttribute(mlp_kernel, cudaFuncAttributeMaxDynamicSharedMemorySize, 96 * 1024);
    dim3 grid((N_ATOMS + TB - 1) / TB, N_ELEM);
    mlp_kernel<<<grid, MLP_THREADS, smem_bytes>>>(
        fingerprints, image_idx, W0, b0, W1, b1, W2, b2, out);

    // sparse force accumulation
    force_kernel<<<1024, 256>>>(fprime_rows, fprime_cols, fprime_vals, nnz, out + N_IMG);
}

// round 4
// speedup vs baseline: 1.1731x; 1.1731x over previous
#include <cuda_runtime.h>

#define N_ATOMS 50000
#define IN_DIM 128
#define HID 256
#define N_ELEM 4
#define N_IMG 500
#define TB 32            // atoms per MLP block
#define MLP_THREADS 256

typedef unsigned long long ull;

// ---------------- packed f32x2 helpers (SASS FFMA2 path) ----------------
__device__ __forceinline__ ull ffma2(ull a, ull b, ull c) {
    ull d;
    asm("fma.rn.f32x2 %0, %1, %2, %3;" : "=l"(d) : "l"(a), "l"(b), "l"(c));
    return d;
}
__device__ __forceinline__ ull splat_f2(float x) {
    ull r;
    asm("mov.b64 %0, {%1, %1};" : "=l"(r) : "f"(x));
    return r;
}
__device__ __forceinline__ float2 unpack2(ull v) {
    float2 f;
    asm("mov.b64 {%0, %1}, %2;" : "=f"(f.x), "=f"(f.y) : "l"(v));
    return f;
}

// ---------------- device scratch (static allocs only) ----------------
__device__ float d_g[N_ATOMS * IN_DIM];            // dE/dfp, 25.6 MB (L2-resident)
__device__ float d_W0T[N_ELEM * HID * IN_DIM];     // W0^T  [e][h][d]
__device__ float d_W1T[N_ELEM * HID * HID];        // W1^T  [e][j][i]
__device__ int   d_perm[N_ATOMS];                  // atoms grouped by element
__device__ int   d_offsets[N_ELEM];
__device__ int   d_counts[N_ELEM];
__device__ int   d_cursor[N_ELEM];

__device__ __forceinline__ int elem_of(int z) {
    return (z == 1) ? 0 : (z == 6) ? 1 : (z == 8) ? 2 : 3;
}

// ---------------- misc kernels ----------------
__global__ void zero_kernel(float* __restrict__ out, int n) {
    int i = blockIdx.x * blockDim.x + threadIdx.x;
    if (i < n) out[i] = 0.0f;
}

__global__ void count_kernel(const int* __restrict__ z, int n) {
    __shared__ int c[N_ELEM];
    int tid = threadIdx.x;
    if (tid < N_ELEM) c[tid] = 0;
    __syncthreads();
    for (int i = tid; i < n; i += blockDim.x)
        atomicAdd(&c[elem_of(z[i])], 1);
    __syncthreads();
    if (tid == 0) {
        int off = 0;
        for (int e = 0; e < N_ELEM; e++) {
            d_offsets[e] = off;
            d_counts[e]  = c[e];
            d_cursor[e]  = off;
            off += c[e];
        }
    }
}

__global__ void scatter_kernel(const int* __restrict__ z, int n) {
    int a = blockIdx.x * blockDim.x + threadIdx.x;
    bool valid = a < n;
    int myE = valid ? elem_of(z[a]) : -1;
    int lane = threadIdx.x & 31;
    #pragma unroll
    for (int e = 0; e < N_ELEM; e++) {
        unsigned m = __ballot_sync(0xffffffffu, myE == e);
        if (!m) continue;
        int leader = __ffs(m) - 1;
        int base = 0;
        if (lane == leader) base = atomicAdd(&d_cursor[e], __popc(m));
        base = __shfl_sync(0xffffffffu, base, leader);
        if (myE == e) {
            int rank = __popc(m & ((1u << lane) - 1u));
            d_perm[base + rank] = a;
        }
    }
}

__global__ void transpose_kernel(const float* __restrict__ W0,
                                 const float* __restrict__ W1) {
    int i = blockIdx.x * blockDim.x + threadIdx.x;
    const int n0 = N_ELEM * IN_DIM * HID;
    const int n1 = N_ELEM * HID * HID;
    if (i < n0) {
        int e = i / (IN_DIM * HID);
        int r = i % (IN_DIM * HID);
        int d = r / HID, h = r % HID;
        d_W0T[e * (HID * IN_DIM) + h * IN_DIM + d] = W0[i];
    }
    if (i < n1) {
        int e = i / (HID * HID);
        int r = i % (HID * HID);
        int ii = r / HID, jj = r % HID;
        d_W1T[e * (HID * HID) + jj * HID + ii] = W1[i];
    }
}

// ---------------- fused per-element MLP fwd + bwd (f32x2 packed) ----------------
// Block: 32 atoms of one element, 256 threads.
// Thread tiling: ag = tid>>5 -> 4 atoms (a0=4*ag), jg = tid&31 -> 8 outputs (j0=8*jg),
// accumulated as 4 packed f32x2 per atom.
__global__ void __launch_bounds__(MLP_THREADS, 2)
mlp_kernel(const float* __restrict__ fp,
           const int*   __restrict__ image_idx,
           const float* __restrict__ W0, const float* __restrict__ b0,
           const float* __restrict__ W1, const float* __restrict__ b1,
           const float* __restrict__ W2, const float* __restrict__ b2,
           float* __restrict__ out_energy)
{
    const int e = blockIdx.y;
    const int cnt = d_counts[e];
    const int start = blockIdx.x * TB;
    if (start >= cnt) return;
    const int off = d_offsets[e];
    const int na  = min(TB, cnt - start);

    extern __shared__ float sm[];
    float* fp_s  = sm;                  // [TB][IN_DIM]   4096 f
    float* h0_s  = sm + 4096;           // [TB][HID]      8192 f  (later holds dh0)
    float* dh1_s = sm + 4096 + 8192;    // [TB][HID]      8192 f
    float* o_s   = sm + 4096 + 16384;   // [TB]
    int*   aidx  = (int*)(o_s + TB);    // [TB]

    const int tid = threadIdx.x;
    if (tid < TB) {
        int a = d_perm[off + start + ((tid < na) ? tid : 0)];
        aidx[tid] = a;
        o_s[tid]  = 0.0f;
    }
    __syncthreads();

    // load fingerprint tile (coalesced)
    for (int l = tid; l < TB * IN_DIM; l += MLP_THREADS) {
        int a = l >> 7, d = l & (IN_DIM - 1);
        fp_s[l] = fp[aidx[a] * IN_DIM + d];
    }
    __syncthreads();

    const int ag = tid >> 5, jg = tid & 31;
    const int a0 = ag * 4,  j0 = jg * 8;

    const float* W0e  = W0 + e * (IN_DIM * HID);
    const float* W1e  = W1 + e * (HID * HID);
    const float* W0Te = d_W0T + e * (HID * IN_DIM);
    const float* W1Te = d_W1T + e * (HID * HID);

    ull acc[4][4];

    // ---- layer 0: h0 = tanh(fp @ W0 + b0) ----
    {
        ulonglong2 bA = *(const ulonglong2*)&b0[e * HID + j0];
        ulonglong2 bB = *(const ulonglong2*)&b0[e * HID + j0 + 4];
        #pragma unroll
        for (int ia = 0; ia < 4; ia++) {
            acc[ia][0] = bA.x; acc[ia][1] = bA.y;
            acc[ia][2] = bB.x; acc[ia][3] = bB.y;
        }
    }
    #pragma unroll 4
    for (int d = 0; d < IN_DIM; d++) {
        ulonglong2 wA = *(const ulonglong2*)&W0e[d * HID + j0];
        ulonglong2 wB = *(const ulonglong2*)&W0e[d * HID + j0 + 4];
        #pragma unroll
        for (int ia = 0; ia < 4; ia++) {
            ull fs = splat_f2(fp_s[(a0 + ia) * IN_DIM + d]);
            acc[ia][0] = ffma2(wA.x, fs, acc[ia][0]);
            acc[ia][1] = ffma2(wA.y, fs, acc[ia][1]);
            acc[ia][2] = ffma2(wB.x, fs, acc[ia][2]);
            acc[ia][3] = ffma2(wB.y, fs, acc[ia][3]);
        }
    }
    #pragma unroll
    for (int ia = 0; ia < 4; ia++) {
        float2 p0 = unpack2(acc[ia][0]), p1 = unpack2(acc[ia][1]);
        float2 p2 = unpack2(acc[ia][2]), p3 = unpack2(acc[ia][3]);
        *(float4*)&h0_s[(a0 + ia) * HID + j0] =
            make_float4(tanhf(p0.x), tanhf(p0.y), tanhf(p1.x), tanhf(p1.y));
        *(float4*)&h0_s[(a0 + ia) * HID + j0 + 4] =
            make_float4(tanhf(p2.x), tanhf(p2.y), tanhf(p3.x), tanhf(p3.y));
    }
    __syncthreads();

    // ---- layer 1: h1 = tanh(h0 @ W1 + b1); o += h1.W2; dh1 = W2*(1-h1^2) ----
    {
        ulonglong2 bA = *(const ulonglong2*)&b1[e * HID + j0];
        ulonglong2 bB = *(const ulonglong2*)&b1[e * HID + j0 + 4];
        #pragma unroll
        for (int ia = 0; ia < 4; ia++) {
            acc[ia][0] = bA.x; acc[ia][1] = bA.y;
            acc[ia][2] = bB.x; acc[ia][3] = bB.y;
        }
    }
    #pragma unroll 4
    for (int i = 0; i < HID; i++) {
        ulonglong2 wA = *(const ulonglong2*)&W1e[i * HID + j0];
        ulonglong2 wB = *(const ulonglong2*)&W1e[i * HID + j0 + 4];
        #pragma unroll
        for (int ia = 0; ia < 4; ia++) {
            ull fs = splat_f2(h0_s[(a0 + ia) * HID + i]);
            acc[ia][0] = ffma2(wA.x, fs, acc[ia][0]);
            acc[ia][1] = ffma2(wA.y, fs, acc[ia][1]);
            acc[ia][2] = ffma2(wB.x, fs, acc[ia][2]);
            acc[ia][3] = ffma2(wB.y, fs, acc[ia][3]);
        }
    }
    {
        float4 wA = *(const float4*)&W2[e * HID + j0];
        float4 wB = *(const float4*)&W2[e * HID + j0 + 4];
        float w2r[8] = {wA.x,wA.y,wA.z,wA.w,wB.x,wB.y,wB.z,wB.w};
        #pragma unroll
        for (int ia = 0; ia < 4; ia++) {
            float2 p0 = unpack2(acc[ia][0]), p1 = unpack2(acc[ia][1]);
            float2 p2 = unpack2(acc[ia][2]), p3 = unpack2(acc[ia][3]);
            float pre[8] = {p0.x,p0.y,p1.x,p1.y,p2.x,p2.y,p3.x,p3.y};
            float opart = 0.0f;
            float dh[8];
            #pragma unroll
            for (int j = 0; j < 8; j++) {
                float h1 = tanhf(pre[j]);
                opart += h1 * w2r[j];
                dh[j] = w2r[j] * (1.0f - h1 * h1);
            }
            *(float4*)&dh1_s[(a0 + ia) * HID + j0]     = make_float4(dh[0],dh[1],dh[2],dh[3]);
            *(float4*)&dh1_s[(a0 + ia) * HID + j0 + 4] = make_float4(dh[4],dh[5],dh[6],dh[7]);
            atomicAdd(&o_s[a0 + ia], opart);
        }
    }
    __syncthreads();

    // ---- bwd layer1: dh0 = (1-h0^2) * (dh1 @ W1^T)  (written in-place into h0_s) ----
    const int i0 = jg * 8;
    #pragma unroll
    for (int ia = 0; ia < 4; ia++)
        #pragma unroll
        for (int k = 0; k < 4; k++) acc[ia][k] = 0ULL;   // two packed 0.0f
    #pragma unroll 4
    for (int j = 0; j < HID; j++) {
        ulonglong2 wA = *(const ulonglong2*)&W1Te[j * HID + i0];
        ulonglong2 wB = *(const ulonglong2*)&W1Te[j * HID + i0 + 4];
        #pragma unroll
        for (int ia = 0; ia < 4; ia++) {
            ull fs = splat_f2(dh1_s[(a0 + ia) * HID + j]);
            acc[ia][0] = ffma2(wA.x, fs, acc[ia][0]);
            acc[ia][1] = ffma2(wA.y, fs, acc[ia][1]);
            acc[ia][2] = ffma2(wB.x, fs, acc[ia][2]);
            acc[ia][3] = ffma2(wB.y, fs, acc[ia][3]);
        }
    }
    #pragma unroll
    for (int ia = 0; ia < 4; ia++) {
        float2 p0 = unpack2(acc[ia][0]), p1 = unpack2(acc[ia][1]);
        float2 p2 = unpack2(acc[ia][2]), p3 = unpack2(acc[ia][3]);
        float s[8] = {p0.x,p0.y,p1.x,p1.y,p2.x,p2.y,p3.x,p3.y};
        float v[8];
        #pragma unroll
        for (int jj = 0; jj < 8; jj++) {
            float h0v = h0_s[(a0 + ia) * HID + i0 + jj];
            v[jj] = (1.0f - h0v * h0v) * s[jj];
        }
        *(float4*)&h0_s[(a0 + ia) * HID + i0]     = make_float4(v[0],v[1],v[2],v[3]);
        *(float4*)&h0_s[(a0 + ia) * HID + i0 + 4] = make_float4(v[4],v[5],v[6],v[7]);
    }
    __syncthreads();

    // ---- bwd layer0: g = dh0 @ W0^T  -> d_g[atom][d] ----
    const int d0 = jg * 4;
    ull accg[4][2];
    #pragma unroll
    for (int ia = 0; ia < 4; ia++) { accg[ia][0] = 0ULL; accg[ia][1] = 0ULL; }
    #pragma unroll 4
    for (int i = 0; i < HID; i++) {
        ulonglong2 w = *(const ulonglong2*)&W0Te[i * IN_DIM + d0];
        #pragma unroll
        for (int ia = 0; ia < 4; ia++) {
            ull fs = splat_f2(h0_s[(a0 + ia) * HID + i]);  // dh0
            accg[ia][0] = ffma2(w.x, fs, accg[ia][0]);
            accg[ia][1] = ffma2(w.y, fs, accg[ia][1]);
        }
    }
    #pragma unroll
    for (int ia = 0; ia < 4; ia++) {
        int a = a0 + ia;
        if (a < na) {
            float2 p0 = unpack2(accg[ia][0]), p1 = unpack2(accg[ia][1]);
            *(float4*)&d_g[aidx[a] * IN_DIM + d0] = make_float4(p0.x, p0.y, p1.x, p1.y);
        }
    }

    // ---- energy: atomic segment-sum over images ----
    if (tid < na) {
        float o = o_s[tid] + b2[e];
        atomicAdd(&out_energy[image_idx[aidx[tid]]], o);
    }
}

// ---------------- sparse force scatter: forces = -fprimes^T @ g ----------------
__global__ void force_kernel(const int* __restrict__ rows,
                             const int* __restrict__ cols,
                             const float* __restrict__ vals,
                             int nnz, float* __restrict__ forces) {
    const int2*   r2 = (const int2*)rows;
    const int2*   c2 = (const int2*)cols;
    const float2* v2 = (const float2*)vals;
    const int nnz2 = nnz >> 1;
    int i = blockIdx.x * blockDim.x + threadIdx.x;
    int stride = gridDim.x * blockDim.x;
    for (; i < nnz2; i += stride) {
        int2 r = __ldg(&r2[i]);
        int2 c = __ldg(&c2[i]);
        float2 v = __ldg(&v2[i]);
        atomicAdd(&forces[c.x], -v.x * d_g[r.x]);
        atomicAdd(&forces[c.y], -v.y * d_g[r.y]);
    }
    if ((nnz & 1) && blockIdx.x == 0 && threadIdx.x == 0) {
        int last = nnz - 1;
        atomicAdd(&forces[cols[last]], -vals[last] * d_g[rows[last]]);
    }
}

// ---------------- launch ----------------
extern "C" void kernel_launch(void* const* d_in, const int* in_sizes, int n_in,
                              void* d_out, int out_size) {
    const float* fingerprints = (const float*)d_in[0];
    const int*   atomic_num   = (const int*)  d_in[1];
    const int*   image_idx    = (const int*)  d_in[2];
    const int*   fprime_rows  = (const int*)  d_in[3];
    const int*   fprime_cols  = (const int*)  d_in[4];
    const float* fprime_vals  = (const float*)d_in[5];
    const float* W0 = (const float*)d_in[6];
    const float* b0 = (const float*)d_in[7];
    const float* W1 = (const float*)d_in[8];
    const float* b1 = (const float*)d_in[9];
    const float* W2 = (const float*)d_in[10];
    const float* b2 = (const float*)d_in[11];
    float* out = (float*)d_out;                 // [0,500): energy, [500,150500): forces
    const int nnz = in_sizes[3];

    // out = zeros (out is poisoned; atomics accumulate into it)
    zero_kernel<<<(out_size + 255) / 256, 256>>>(out, out_size);

    // bucket atoms by element
    count_kernel<<<1, 1024>>>(atomic_num, N_ATOMS);
    scatter_kernel<<<(N_ATOMS + 255) / 256, 256>>>(atomic_num, N_ATOMS);

    // weight transposes for coalesced backward GEMMs
    transpose_kernel<<<(N_ELEM * HID * HID + 255) / 256, 256>>>(W0, W1);

    // fused MLP fwd+bwd
    const int smem_bytes = (4096 + 8192 + 8192 + TB) * 4 + TB * 4;
    cudaFuncSetAttribute(mlp_kernel, cudaFuncAttributeMaxDynamicSharedMemorySize, 96 * 1024);
    dim3 grid((N_ATOMS + TB - 1) / TB, N_ELEM);
    mlp_kernel<<<grid, MLP_THREADS, smem_bytes>>>(
        fingerprints, image_idx, W0, b0, W1, b1, W2, b2, out);

    // sparse force accumulation (vectorized x2)
    force_kernel<<<4096, 256>>>(fprime_rows, fprime_cols, fprime_vals, nnz, out + N_IMG);
}

// round 5
// speedup vs baseline: 1.6443x; 1.4017x over previous
#include <cuda_runtime.h>
#include <cuda_bf16.h>
#include <cstdint>

#define N_ATOMS 50000
#define IN_DIM 128
#define HID 256
#define N_ELEM 4
#define N_IMG 500
#define M_BLK 64          // atoms per MLP block
#define MLP_THREADS 256

// ---------------- device scratch (static allocs only) ----------------
__device__ float d_g[(size_t)N_ATOMS * IN_DIM];    // dE/dfp, 25.6 MB
__device__ int   d_perm[N_ATOMS];
__device__ int   d_offsets[N_ELEM];
__device__ int   d_counts[N_ELEM];
__device__ int   d_cursor[N_ELEM];

// fragment-prepacked weights, bf16 hi/lo split.
// layout (u32): [e][part][k16][n8][lane(32)][bidx(2)]
__device__ uint32_t d_B0pk [4 * 2 * 8  * 32 * 64];   // W0   [128k x 256n]  131072
__device__ uint32_t d_B1pk [4 * 2 * 16 * 32 * 64];   // W1   [256k x 256n]  524288
__device__ uint32_t d_BT1pk[4 * 2 * 16 * 32 * 64];   // W1^T [256k x 256n]  524288
__device__ uint32_t d_BT0pk[4 * 2 * 16 * 16 * 64];   // W0^T [256k x 128n]  262144

__device__ __forceinline__ int elem_of(int z) {
    return (z == 1) ? 0 : (z == 6) ? 1 : (z == 8) ? 2 : 3;
}

// ---------------- helpers ----------------
__device__ __forceinline__ void split2(float v0, float v1, uint32_t& hi, uint32_t& lo) {
    __nv_bfloat16 h0 = __float2bfloat16(v0), h1 = __float2bfloat16(v1);
    __nv_bfloat16 l0 = __float2bfloat16(v0 - __bfloat162float(h0));
    __nv_bfloat16 l1 = __float2bfloat16(v1 - __bfloat162float(h1));
    hi = ((uint32_t)__bfloat16_as_ushort(h1) << 16) | (uint32_t)__bfloat16_as_ushort(h0);
    lo = ((uint32_t)__bfloat16_as_ushort(l1) << 16) | (uint32_t)__bfloat16_as_ushort(l0);
}
__device__ __forceinline__ float2 unsplit2(uint32_t hi, uint32_t lo) {
    float a = __bfloat162float(__ushort_as_bfloat16((unsigned short)(hi & 0xffff)))
            + __bfloat162float(__ushort_as_bfloat16((unsigned short)(lo & 0xffff)));
    float b = __bfloat162float(__ushort_as_bfloat16((unsigned short)(hi >> 16)))
            + __bfloat162float(__ushort_as_bfloat16((unsigned short)(lo >> 16)));
    return make_float2(a, b);
}
// A-fragment-packed smem index (b32 units) for (row r in [0,64), col/k n)
__device__ __forceinline__ int apk_idx(int r, int n) {
    return ((((n >> 4) << 2) | (r >> 4)) * 32 + ((r & 7) * 4 + ((n >> 1) & 3))) * 4
           + ((r >> 3) & 1) + (((n >> 3) & 1) << 1);
}

#define MMA_BF16(d, a, b) asm volatile( \
    "mma.sync.aligned.m16n8k16.row.col.f32.bf16.bf16.f32 " \
    "{%0,%1,%2,%3},{%4,%5,%6,%7},{%8,%9},{%0,%1,%2,%3};" \
    : "+f"((d)[0]), "+f"((d)[1]), "+f"((d)[2]), "+f"((d)[3]) \
    : "r"((a).x), "r"((a).y), "r"((a).z), "r"((a).w), "r"((b).x), "r"((b).y))

// ---------------- misc kernels ----------------
__global__ void zero_kernel(float* __restrict__ out, int n) {
    int i = blockIdx.x * blockDim.x + threadIdx.x;
    if (i < n) out[i] = 0.0f;
}

__global__ void count_kernel(const int* __restrict__ z, int n) {
    __shared__ int c[N_ELEM];
    int tid = threadIdx.x;
    if (tid < N_ELEM) c[tid] = 0;
    __syncthreads();
    for (int i = tid; i < n; i += blockDim.x)
        atomicAdd(&c[elem_of(z[i])], 1);
    __syncthreads();
    if (tid == 0) {
        int off = 0;
        for (int e = 0; e < N_ELEM; e++) {
            d_offsets[e] = off; d_counts[e] = c[e]; d_cursor[e] = off;
            off += c[e];
        }
    }
}

__global__ void scatter_kernel(const int* __restrict__ z, int n) {
    int a = blockIdx.x * blockDim.x + threadIdx.x;
    bool valid = a < n;
    int myE = valid ? elem_of(z[a]) : -1;
    int lane = threadIdx.x & 31;
    #pragma unroll
    for (int e = 0; e < N_ELEM; e++) {
        unsigned m = __ballot_sync(0xffffffffu, myE == e);
        if (!m) continue;
        int leader = __ffs(m) - 1;
        int base = 0;
        if (lane == leader) base = atomicAdd(&d_cursor[e], __popc(m));
        base = __shfl_sync(0xffffffffu, base, leader);
        if (myE == e) {
            int rank = __popc(m & ((1u << lane) - 1u));
            d_perm[base + rank] = a;
        }
    }
}

// pre-split + fragment-pack all weight matrices
__global__ void prep_kernel(const float* __restrict__ W0, const float* __restrict__ W1) {
    const int C0 = 131072, C1 = 524288, C2 = 524288, C3 = 262144;
    int i = blockIdx.x * blockDim.x + threadIdx.x;
    uint32_t* dst; int K16, N8, idx, mode;
    if      (i < C0)                { dst = d_B0pk;  K16 = 8;  N8 = 32; idx = i;                mode = 0; }
    else if (i < C0 + C1)           { dst = d_B1pk;  K16 = 16; N8 = 32; idx = i - C0;           mode = 1; }
    else if (i < C0 + C1 + C2)      { dst = d_BT1pk; K16 = 16; N8 = 32; idx = i - C0 - C1;      mode = 2; }
    else if (i < C0 + C1 + C2 + C3) { dst = d_BT0pk; K16 = 16; N8 = 16; idx = i - C0 - C1 - C2; mode = 3; }
    else return;
    int bidx = idx & 1;
    int lane = (idx >> 1) & 31;
    int rest = idx >> 6;
    int n8  = rest % N8;  rest /= N8;
    int k16 = rest % K16; rest /= K16;
    int part = rest & 1;
    int e    = rest >> 1;
    int gg = lane >> 2, tIG = lane & 3;
    int n = n8 * 8 + gg;
    int k = k16 * 16 + bidx * 8 + tIG * 2;
    float w0, w1;
    if (mode == 0)      { const float* B = W0 + e * 32768; w0 = B[k * 256 + n]; w1 = B[(k + 1) * 256 + n]; }
    else if (mode == 1) { const float* B = W1 + e * 65536; w0 = B[k * 256 + n]; w1 = B[(k + 1) * 256 + n]; }
    else if (mode == 2) { const float* B = W1 + e * 65536; w0 = B[n * 256 + k]; w1 = B[n * 256 + k + 1]; }
    else                { const float* B = W0 + e * 32768; w0 = B[n * 256 + k]; w1 = B[n * 256 + k + 1]; }
    __nv_bfloat16 h0 = __float2bfloat16(w0), h1 = __float2bfloat16(w1);
    __nv_bfloat16 v0, v1;
    if (part == 0) { v0 = h0; v1 = h1; }
    else {
        v0 = __float2bfloat16(w0 - __bfloat162float(h0));
        v1 = __float2bfloat16(w1 - __bfloat162float(h1));
    }
    dst[idx] = ((uint32_t)__bfloat16_as_ushort(v1) << 16) | (uint32_t)__bfloat16_as_ushort(v0);
}

// ---------------- GEMM phase (bf16x3: hi*hi + hi*lo + lo*hi) ----------------
template <int K16, int NF, int N8TOT>
__device__ __forceinline__ void gemm_phase(
    const uint32_t* __restrict__ As, int psA,     // smem, A packed (hi at 0, lo at psA)
    const uint32_t* __restrict__ Bg, int psB,     // global, B packed
    int r16base, int n8base, int lane, float acc[2][8][4])
{
    for (int k16 = 0; k16 < K16; k16++) {
        uint4 ahi[2], alo[2];
        #pragma unroll
        for (int mf = 0; mf < 2; mf++) {
            int b = ((k16 * 4 + r16base + mf) * 32 + lane) * 4;
            ahi[mf] = *(const uint4*)&As[b];
            alo[mf] = *(const uint4*)&As[psA + b];
        }
        #pragma unroll
        for (int nf = 0; nf < NF; nf++) {
            int bb = ((k16 * N8TOT + n8base + nf) * 32 + lane) * 2;
            uint2 bhi = *(const uint2*)&Bg[bb];
            uint2 blo = *(const uint2*)&Bg[psB + bb];
            MMA_BF16(acc[0][nf], ahi[0], bhi);
            MMA_BF16(acc[1][nf], ahi[1], bhi);
            MMA_BF16(acc[0][nf], ahi[0], blo);
            MMA_BF16(acc[1][nf], ahi[1], blo);
            MMA_BF16(acc[0][nf], alo[0], bhi);
            MMA_BF16(acc[1][nf], alo[1], bhi);
        }
    }
}

// ---------------- fused MLP fwd + bwd, tensor-core ----------------
// block: 64 atoms, 256 threads = 8 warps in 2(M) x 4(N) grid; warp tile 32x64 (32x32 for B0).
__global__ void __launch_bounds__(MLP_THREADS)
mlp_mma_kernel(const float* __restrict__ fp, const int* __restrict__ image_idx,
               const float* __restrict__ b0g, const float* __restrict__ b1g,
               const float* __restrict__ W2g, const float* __restrict__ b2g,
               float* __restrict__ out_energy)
{
    const int e = blockIdx.y;
    const int cnt = d_counts[e];
    const int start = blockIdx.x * M_BLK;
    if (start >= cnt) return;
    const int off = d_offsets[e];
    const int na = min(M_BLK, cnt - start);

    extern __shared__ uint32_t smu[];
    uint32_t* buf0 = smu;              // 16384 u32 = 64KB : h0 packed -> dh0 packed
    uint32_t* buf1 = smu + 16384;      // 16384 u32 = 64KB : fpA packed -> dh1 packed
    float*    o_s  = (float*)(smu + 32768);   // [64]
    int*      aidx = (int*)(o_s + M_BLK);     // [64]

    const int tid = threadIdx.x;
    const int warp = tid >> 5, lane = tid & 31;
    const int gg = lane >> 2, tIG = lane & 3;
    const int warpM = warp >> 2, warpN = warp & 3;
    const int r16base = warpM * 2;

    if (tid < M_BLK) {
        aidx[tid] = d_perm[off + start + min(tid, na - 1)];
        o_s[tid] = 0.0f;
    }
    __syncthreads();

    // ---- stage fingerprint tile as packed bf16 hi/lo A fragments (K=128, psA=4096) ----
    for (int p = tid; p < M_BLK * 64; p += MLP_THREADS) {
        int r = p >> 6, kp = p & 63;
        float2 v = *(const float2*)&fp[(size_t)aidx[r] * IN_DIM + 2 * kp];
        uint32_t hi, lo; split2(v.x, v.y, hi, lo);
        int idx = apk_idx(r, 2 * kp);
        buf1[idx] = hi; buf1[4096 + idx] = lo;
    }
    __syncthreads();

    float acc[2][8][4];

    // ================= L0: preact0 = fpA @ W0 + b0 =================
    #pragma unroll
    for (int nf = 0; nf < 8; nf++) {
        int n0 = warpN * 64 + nf * 8 + 2 * tIG;
        float2 bb = *(const float2*)&b0g[e * HID + n0];
        acc[0][nf][0] = bb.x; acc[0][nf][1] = bb.y; acc[0][nf][2] = bb.x; acc[0][nf][3] = bb.y;
        acc[1][nf][0] = bb.x; acc[1][nf][1] = bb.y; acc[1][nf][2] = bb.x; acc[1][nf][3] = bb.y;
    }
    gemm_phase<8, 8, 32>(buf1, 4096, d_B0pk + e * 32768, 16384, r16base, warpN * 8, lane, acc);
    // epilogue: h0 = tanh -> packed into buf0 (K=256 layout, psA=8192)
    #pragma unroll
    for (int mf = 0; mf < 2; mf++) {
        int r0 = warpM * 32 + mf * 16 + gg, r1 = r0 + 8;
        #pragma unroll
        for (int nf = 0; nf < 8; nf++) {
            int n0 = warpN * 64 + nf * 8 + 2 * tIG;
            float t0 = tanhf(acc[mf][nf][0]), t1 = tanhf(acc[mf][nf][1]);
            float t2 = tanhf(acc[mf][nf][2]), t3 = tanhf(acc[mf][nf][3]);
            uint32_t hi, lo;
            split2(t0, t1, hi, lo);
            int i0 = apk_idx(r0, n0); buf0[i0] = hi; buf0[8192 + i0] = lo;
            split2(t2, t3, hi, lo);
            int i1 = apk_idx(r1, n0); buf0[i1] = hi; buf0[8192 + i1] = lo;
        }
    }
    __syncthreads();

    // ================= L1: preact1 = h0 @ W1 + b1 =================
    #pragma unroll
    for (int nf = 0; nf < 8; nf++) {
        int n0 = warpN * 64 + nf * 8 + 2 * tIG;
        float2 bb = *(const float2*)&b1g[e * HID + n0];
        acc[0][nf][0] = bb.x; acc[0][nf][1] = bb.y; acc[0][nf][2] = bb.x; acc[0][nf][3] = bb.y;
        acc[1][nf][0] = bb.x; acc[1][nf][1] = bb.y; acc[1][nf][2] = bb.x; acc[1][nf][3] = bb.y;
    }
    gemm_phase<16, 8, 32>(buf0, 8192, d_B1pk + e * 65536, 32768, r16base, warpN * 8, lane, acc);
    // epilogue: h1 = tanh; o += h1.W2; dh1 = W2*(1-h1^2) -> packed into buf1 (psA=8192)
    #pragma unroll
    for (int mf = 0; mf < 2; mf++) {
        int r0 = warpM * 32 + mf * 16 + gg, r1 = r0 + 8;
        float orow0 = 0.0f, orow1 = 0.0f;
        #pragma unroll
        for (int nf = 0; nf < 8; nf++) {
            int n0 = warpN * 64 + nf * 8 + 2 * tIG;
            float2 w2v = *(const float2*)&W2g[e * HID + n0];
            float t0 = tanhf(acc[mf][nf][0]), t1 = tanhf(acc[mf][nf][1]);
            float t2 = tanhf(acc[mf][nf][2]), t3 = tanhf(acc[mf][nf][3]);
            orow0 += t0 * w2v.x + t1 * w2v.y;
            orow1 += t2 * w2v.x + t3 * w2v.y;
            float d0 = w2v.x * (1.0f - t0 * t0), d1 = w2v.y * (1.0f - t1 * t1);
            float d2 = w2v.x * (1.0f - t2 * t2), d3 = w2v.y * (1.0f - t3 * t3);
            uint32_t hi, lo;
            split2(d0, d1, hi, lo);
            int i0 = apk_idx(r0, n0); buf1[i0] = hi; buf1[8192 + i0] = lo;
            split2(d2, d3, hi, lo);
            int i1 = apk_idx(r1, n0); buf1[i1] = hi; buf1[8192 + i1] = lo;
        }
        atomicAdd(&o_s[r0], orow0);
        atomicAdd(&o_s[r1], orow1);
    }
    __syncthreads();

    // energy: atomic segment-sum over images
    if (tid < na)
        atomicAdd(&out_energy[image_idx[aidx[tid]]], o_s[tid] + b2g[e]);

    // ================= B1: t = dh1 @ W1^T; dh0 = (1-h0^2)*t =================
    #pragma unroll
    for (int mf = 0; mf < 2; mf++)
        #pragma unroll
        for (int nf = 0; nf < 8; nf++)
            #pragma unroll
            for (int q = 0; q < 4; q++) acc[mf][nf][q] = 0.0f;
    gemm_phase<16, 8, 32>(buf1, 8192, d_BT1pk + e * 65536, 32768, r16base, warpN * 8, lane, acc);
    #pragma unroll
    for (int mf = 0; mf < 2; mf++) {
        int r0 = warpM * 32 + mf * 16 + gg, r1 = r0 + 8;
        #pragma unroll
        for (int nf = 0; nf < 8; nf++) {
            int n0 = warpN * 64 + nf * 8 + 2 * tIG;
            int i0 = apk_idx(r0, n0), i1 = apk_idx(r1, n0);
            float2 h0a = unsplit2(buf0[i0], buf0[8192 + i0]);
            float2 h0b = unsplit2(buf0[i1], buf0[8192 + i1]);
            float v0 = (1.0f - h0a.x * h0a.x) * acc[mf][nf][0];
            float v1 = (1.0f - h0a.y * h0a.y) * acc[mf][nf][1];
            float v2 = (1.0f - h0b.x * h0b.x) * acc[mf][nf][2];
            float v3 = (1.0f - h0b.y * h0b.y) * acc[mf][nf][3];
            uint32_t hi, lo;
            split2(v0, v1, hi, lo); buf0[i0] = hi; buf0[8192 + i0] = lo;
            split2(v2, v3, hi, lo); buf0[i1] = hi; buf0[8192 + i1] = lo;
        }
    }
    __syncthreads();

    // ================= B0: g = dh0 @ W0^T -> d_g =================
    #pragma unroll
    for (int mf = 0; mf < 2; mf++)
        #pragma unroll
        for (int nf = 0; nf < 4; nf++)
            #pragma unroll
            for (int q = 0; q < 4; q++) acc[mf][nf][q] = 0.0f;
    gemm_phase<16, 4, 16>(buf0, 8192, d_BT0pk + e * 32768, 16384, r16base, warpN * 4, lane, acc);
    #pragma unroll
    for (int mf = 0; mf < 2; mf++) {
        int r0 = warpM * 32 + mf * 16 + gg, r1 = r0 + 8;
        #pragma unroll
        for (int nf = 0; nf < 4; nf++) {
            int n0 = warpN * 32 + nf * 8 + 2 * tIG;
            if (r0 < na)
                *(float2*)&d_g[(size_t)aidx[r0] * IN_DIM + n0] =
                    make_float2(acc[mf][nf][0], acc[mf][nf][1]);
            if (r1 < na)
                *(float2*)&d_g[(size_t)aidx[r1] * IN_DIM + n0] =
                    make_float2(acc[mf][nf][2], acc[mf][nf][3]);
        }
    }
}

// ---------------- sparse force scatter: forces = -fprimes^T @ g ----------------
__global__ void force_kernel(const int* __restrict__ rows,
                             const int* __restrict__ cols,
                             const float* __restrict__ vals,
                             int nnz, float* __restrict__ forces) {
    const int2*   r2 = (const int2*)rows;
    const int2*   c2 = (const int2*)cols;
    const float2* v2 = (const float2*)vals;
    const int nnz2 = nnz >> 1;
    int i = blockIdx.x * blockDim.x + threadIdx.x;
    int stride = gridDim.x * blockDim.x;
    for (; i < nnz2; i += stride) {
        int2 r = __ldg(&r2[i]);
        int2 c = __ldg(&c2[i]);
        float2 v = __ldg(&v2[i]);
        atomicAdd(&forces[c.x], -v.x * d_g[r.x]);
        atomicAdd(&forces[c.y], -v.y * d_g[r.y]);
    }
    if ((nnz & 1) && blockIdx.x == 0 && threadIdx.x == 0) {
        int last = nnz - 1;
        atomicAdd(&forces[cols[last]], -vals[last] * d_g[rows[last]]);
    }
}

// ---------------- launch ----------------
extern "C" void kernel_launch(void* const* d_in, const int* in_sizes, int n_in,
                              void* d_out, int out_size) {
    const float* fingerprints = (const float*)d_in[0];
    const int*   atomic_num   = (const int*)  d_in[1];
    const int*   image_idx    = (const int*)  d_in[2];
    const int*   fprime_rows  = (const int*)  d_in[3];
    const int*   fprime_cols  = (const int*)  d_in[4];
    const float* fprime_vals  = (const float*)d_in[5];
    const float* W0 = (const float*)d_in[6];
    const float* b0 = (const float*)d_in[7];
    const float* W1 = (const float*)d_in[8];
    const float* b1 = (const float*)d_in[9];
    const float* W2 = (const float*)d_in[10];
    const float* b2 = (const float*)d_in[11];
    float* out = (float*)d_out;                 // [0,500): energy, [500,150500): forces
    const int nnz = in_sizes[3];

    zero_kernel<<<(out_size + 255) / 256, 256>>>(out, out_size);

    count_kernel<<<1, 1024>>>(atomic_num, N_ATOMS);
    scatter_kernel<<<(N_ATOMS + 255) / 256, 256>>>(atomic_num, N_ATOMS);

    // split + fragment-pack weights (1,441,792 u32 outputs)
    prep_kernel<<<(1441792 + 255) / 256, 256>>>(W0, W1);

    // fused tensor-core MLP fwd+bwd
    const int smem_bytes = (32768 + M_BLK + M_BLK) * 4;   // 131,584 B
    cudaFuncSetAttribute(mlp_mma_kernel, cudaFuncAttributeMaxDynamicSharedMemorySize, 136 * 1024);
    dim3 grid((N_ATOMS + M_BLK - 1) / M_BLK, N_ELEM);
    mlp_mma_kernel<<<grid, MLP_THREADS, smem_bytes>>>(
        fingerprints, image_idx, b0, b1, W2, b2, out);

    // sparse force accumulation (vectorized x2)
    force_kernel<<<4096, 256>>>(fprime_rows, fprime_cols, fprime_vals, nnz, out + N_IMG);
}

// round 6
// speedup vs baseline: 3.1944x; 1.9427x over previous
#include <cuda_runtime.h>
#include <cuda_bf16.h>
#include <cstdint>

#define N_ATOMS 50000
#define IN_DIM 128
#define HID 256
#define N_ELEM 4
#define N_IMG 500
#define M_BLK 64          // atoms per MLP block
#define MLP_THREADS 512   // 16 warps: 2(M) x 8(N)

// ---------------- device scratch (static allocs only) ----------------
__device__ float d_g[(size_t)N_ATOMS * IN_DIM];    // dE/dfp, 25.6 MB
__device__ int   d_perm[N_ATOMS];
__device__ int   d_offsets[N_ELEM];
__device__ int   d_counts[N_ELEM];
__device__ int   d_cursor[N_ELEM];

// fragment-prepacked weights, bf16 hi/lo split.
// layout (u32): [e][part][k16][n8][lane(32)][bidx(2)]
__device__ uint32_t d_B0pk [4 * 2 * 8  * 32 * 64];   // W0   [128k x 256n]  131072
__device__ uint32_t d_B1pk [4 * 2 * 16 * 32 * 64];   // W1   [256k x 256n]  524288
__device__ uint32_t d_BT1pk[4 * 2 * 16 * 32 * 64];   // W1^T [256k x 256n]  524288
__device__ uint32_t d_BT0pk[4 * 2 * 16 * 16 * 64];   // W0^T [256k x 128n]  262144

__device__ __forceinline__ int elem_of(int z) {
    return (z == 1) ? 0 : (z == 6) ? 1 : (z == 8) ? 2 : 3;
}

// ---------------- helpers ----------------
__device__ __forceinline__ void split2(float v0, float v1, uint32_t& hi, uint32_t& lo) {
    __nv_bfloat16 h0 = __float2bfloat16(v0), h1 = __float2bfloat16(v1);
    __nv_bfloat16 l0 = __float2bfloat16(v0 - __bfloat162float(h0));
    __nv_bfloat16 l1 = __float2bfloat16(v1 - __bfloat162float(h1));
    hi = ((uint32_t)__bfloat16_as_ushort(h1) << 16) | (uint32_t)__bfloat16_as_ushort(h0);
    lo = ((uint32_t)__bfloat16_as_ushort(l1) << 16) | (uint32_t)__bfloat16_as_ushort(l0);
}
__device__ __forceinline__ float2 unsplit2(uint32_t hi, uint32_t lo) {
    float a = __bfloat162float(__ushort_as_bfloat16((unsigned short)(hi & 0xffff)))
            + __bfloat162float(__ushort_as_bfloat16((unsigned short)(lo & 0xffff)));
    float b = __bfloat162float(__ushort_as_bfloat16((unsigned short)(hi >> 16)))
            + __bfloat162float(__ushort_as_bfloat16((unsigned short)(lo >> 16)));
    return make_float2(a, b);
}
// A-fragment-packed smem index (b32 units) for (row r in [0,64), col/k n)
__device__ __forceinline__ int apk_idx(int r, int n) {
    return ((((n >> 4) << 2) | (r >> 4)) * 32 + ((r & 7) * 4 + ((n >> 1) & 3))) * 4
           + ((r >> 3) & 1) + (((n >> 3) & 1) << 1);
}

#define MMA_BF16(d, a, b) asm volatile( \
    "mma.sync.aligned.m16n8k16.row.col.f32.bf16.bf16.f32 " \
    "{%0,%1,%2,%3},{%4,%5,%6,%7},{%8,%9},{%0,%1,%2,%3};" \
    : "+f"((d)[0]), "+f"((d)[1]), "+f"((d)[2]), "+f"((d)[3]) \
    : "r"((a).x), "r"((a).y), "r"((a).z), "r"((a).w), "r"((b).x), "r"((b).y))

// ---------------- misc kernels ----------------
__global__ void zero_kernel(float* __restrict__ out, int n) {
    int i = blockIdx.x * blockDim.x + threadIdx.x;
    if (i < n) out[i] = 0.0f;
}

__global__ void count_kernel(const int* __restrict__ z, int n) {
    __shared__ int c[N_ELEM];
    int tid = threadIdx.x;
    if (tid < N_ELEM) c[tid] = 0;
    __syncthreads();
    for (int i = tid; i < n; i += blockDim.x)
        atomicAdd(&c[elem_of(z[i])], 1);
    __syncthreads();
    if (tid == 0) {
        int off = 0;
        for (int e = 0; e < N_ELEM; e++) {
            d_offsets[e] = off; d_counts[e] = c[e]; d_cursor[e] = off;
            off += c[e];
        }
    }
}

__global__ void scatter_kernel(const int* __restrict__ z, int n) {
    int a = blockIdx.x * blockDim.x + threadIdx.x;
    bool valid = a < n;
    int myE = valid ? elem_of(z[a]) : -1;
    int lane = threadIdx.x & 31;
    #pragma unroll
    for (int e = 0; e < N_ELEM; e++) {
        unsigned m = __ballot_sync(0xffffffffu, myE == e);
        if (!m) continue;
        int leader = __ffs(m) - 1;
        int base = 0;
        if (lane == leader) base = atomicAdd(&d_cursor[e], __popc(m));
        base = __shfl_sync(0xffffffffu, base, leader);
        if (myE == e) {
            int rank = __popc(m & ((1u << lane) - 1u));
            d_perm[base + rank] = a;
        }
    }
}

// pre-split + fragment-pack all weight matrices
__global__ void prep_kernel(const float* __restrict__ W0, const float* __restrict__ W1) {
    const int C0 = 131072, C1 = 524288, C2 = 524288, C3 = 262144;
    int i = blockIdx.x * blockDim.x + threadIdx.x;
    uint32_t* dst; int K16, N8, idx, mode;
    if      (i < C0)                { dst = d_B0pk;  K16 = 8;  N8 = 32; idx = i;                mode = 0; }
    else if (i < C0 + C1)           { dst = d_B1pk;  K16 = 16; N8 = 32; idx = i - C0;           mode = 1; }
    else if (i < C0 + C1 + C2)      { dst = d_BT1pk; K16 = 16; N8 = 32; idx = i - C0 - C1;      mode = 2; }
    else if (i < C0 + C1 + C2 + C3) { dst = d_BT0pk; K16 = 16; N8 = 16; idx = i - C0 - C1 - C2; mode = 3; }
    else return;
    int bidx = idx & 1;
    int lane = (idx >> 1) & 31;
    int rest = idx >> 6;
    int n8  = rest % N8;  rest /= N8;
    int k16 = rest % K16; rest /= K16;
    int part = rest & 1;
    int e    = rest >> 1;
    int gg = lane >> 2, tIG = lane & 3;
    int n = n8 * 8 + gg;
    int k = k16 * 16 + bidx * 8 + tIG * 2;
    float w0, w1;
    if (mode == 0)      { const float* B = W0 + e * 32768; w0 = B[k * 256 + n]; w1 = B[(k + 1) * 256 + n]; }
    else if (mode == 1) { const float* B = W1 + e * 65536; w0 = B[k * 256 + n]; w1 = B[(k + 1) * 256 + n]; }
    else if (mode == 2) { const float* B = W1 + e * 65536; w0 = B[n * 256 + k]; w1 = B[n * 256 + k + 1]; }
    else                { const float* B = W0 + e * 32768; w0 = B[n * 256 + k]; w1 = B[n * 256 + k + 1]; }
    __nv_bfloat16 h0 = __float2bfloat16(w0), h1 = __float2bfloat16(w1);
    __nv_bfloat16 v0, v1;
    if (part == 0) { v0 = h0; v1 = h1; }
    else {
        v0 = __float2bfloat16(w0 - __bfloat162float(h0));
        v1 = __float2bfloat16(w1 - __bfloat162float(h1));
    }
    dst[idx] = ((uint32_t)__bfloat16_as_ushort(v1) << 16) | (uint32_t)__bfloat16_as_ushort(v0);
}

// ---------------- GEMM phase (bf16x3: hi*hi + hi*lo + lo*hi) ----------------
template <int K16, int NF, int N8TOT>
__device__ __forceinline__ void gemm_phase(
    const uint32_t* __restrict__ As, int psA,     // smem, A packed (hi at 0, lo at psA)
    const uint32_t* __restrict__ Bg, int psB,     // global, B packed
    int r16base, int n8base, int lane, float (&acc)[2][4][4])
{
    #pragma unroll 2
    for (int k16 = 0; k16 < K16; k16++) {
        uint4 ahi[2], alo[2];
        #pragma unroll
        for (int mf = 0; mf < 2; mf++) {
            int b = ((k16 * 4 + r16base + mf) * 32 + lane) * 4;
            ahi[mf] = *(const uint4*)&As[b];
            alo[mf] = *(const uint4*)&As[psA + b];
        }
        #pragma unroll
        for (int nf = 0; nf < NF; nf++) {
            int bb = ((k16 * N8TOT + n8base + nf) * 32 + lane) * 2;
            uint2 bhi = *(const uint2*)&Bg[bb];
            uint2 blo = *(const uint2*)&Bg[psB + bb];
            MMA_BF16(acc[0][nf], ahi[0], bhi);
            MMA_BF16(acc[1][nf], ahi[1], bhi);
            MMA_BF16(acc[0][nf], ahi[0], blo);
            MMA_BF16(acc[1][nf], ahi[1], blo);
            MMA_BF16(acc[0][nf], alo[0], bhi);
            MMA_BF16(acc[1][nf], alo[1], bhi);
        }
    }
}

// ---------------- fused MLP fwd + bwd, tensor-core ----------------
// block: 64 atoms, 512 threads = 16 warps in 2(M) x 8(N) grid; warp tile 32x32 (32x16 for B0).
__global__ void __launch_bounds__(MLP_THREADS)
mlp_mma_kernel(const float* __restrict__ fp, const int* __restrict__ image_idx,
               const float* __restrict__ b0g, const float* __restrict__ b1g,
               const float* __restrict__ W2g, const float* __restrict__ b2g,
               float* __restrict__ out_energy)
{
    const int e = blockIdx.y;
    const int cnt = d_counts[e];
    const int start = blockIdx.x * M_BLK;
    if (start >= cnt) return;
    const int off = d_offsets[e];
    const int na = min(M_BLK, cnt - start);

    extern __shared__ uint32_t smu[];
    uint32_t* buf0 = smu;              // 16384 u32 = 64KB : h0 packed -> dh0 packed
    uint32_t* buf1 = smu + 16384;      // 16384 u32 = 64KB : fpA packed -> dh1 packed
    float*    o_s  = (float*)(smu + 32768);   // [64]
    int*      aidx = (int*)(o_s + M_BLK);     // [64]

    const int tid = threadIdx.x;
    const int warp = tid >> 5, lane = tid & 31;
    const int gg = lane >> 2, tIG = lane & 3;
    const int warpM = warp >> 3, warpN = warp & 7;
    const int r16base = warpM * 2;

    if (tid < M_BLK) {
        aidx[tid] = d_perm[off + start + min(tid, na - 1)];
        o_s[tid] = 0.0f;
    }
    __syncthreads();

    // ---- stage fingerprint tile as packed bf16 hi/lo A fragments (K=128, psA=4096) ----
    for (int p = tid; p < M_BLK * 64; p += MLP_THREADS) {
        int r = p >> 6, kp = p & 63;
        float2 v = *(const float2*)&fp[(size_t)aidx[r] * IN_DIM + 2 * kp];
        uint32_t hi, lo; split2(v.x, v.y, hi, lo);
        int idx = apk_idx(r, 2 * kp);
        buf1[idx] = hi; buf1[4096 + idx] = lo;
    }
    __syncthreads();

    float acc[2][4][4];

    // ================= L0: preact0 = fpA @ W0 + b0 =================
    #pragma unroll
    for (int nf = 0; nf < 4; nf++) {
        int n0 = warpN * 32 + nf * 8 + 2 * tIG;
        float2 bb = *(const float2*)&b0g[e * HID + n0];
        acc[0][nf][0] = bb.x; acc[0][nf][1] = bb.y; acc[0][nf][2] = bb.x; acc[0][nf][3] = bb.y;
        acc[1][nf][0] = bb.x; acc[1][nf][1] = bb.y; acc[1][nf][2] = bb.x; acc[1][nf][3] = bb.y;
    }
    gemm_phase<8, 4, 32>(buf1, 4096, d_B0pk + e * 32768, 16384, r16base, warpN * 4, lane, acc);
    // epilogue: h0 = tanh -> packed into buf0 (K=256 layout, psA=8192)
    #pragma unroll
    for (int mf = 0; mf < 2; mf++) {
        int r0 = warpM * 32 + mf * 16 + gg, r1 = r0 + 8;
        #pragma unroll
        for (int nf = 0; nf < 4; nf++) {
            int n0 = warpN * 32 + nf * 8 + 2 * tIG;
            float t0 = tanhf(acc[mf][nf][0]), t1 = tanhf(acc[mf][nf][1]);
            float t2 = tanhf(acc[mf][nf][2]), t3 = tanhf(acc[mf][nf][3]);
            uint32_t hi, lo;
            split2(t0, t1, hi, lo);
            int i0 = apk_idx(r0, n0); buf0[i0] = hi; buf0[8192 + i0] = lo;
            split2(t2, t3, hi, lo);
            int i1 = apk_idx(r1, n0); buf0[i1] = hi; buf0[8192 + i1] = lo;
        }
    }
    __syncthreads();

    // ================= L1: preact1 = h0 @ W1 + b1 =================
    #pragma unroll
    for (int nf = 0; nf < 4; nf++) {
        int n0 = warpN * 32 + nf * 8 + 2 * tIG;
        float2 bb = *(const float2*)&b1g[e * HID + n0];
        acc[0][nf][0] = bb.x; acc[0][nf][1] = bb.y; acc[0][nf][2] = bb.x; acc[0][nf][3] = bb.y;
        acc[1][nf][0] = bb.x; acc[1][nf][1] = bb.y; acc[1][nf][2] = bb.x; acc[1][nf][3] = bb.y;
    }
    gemm_phase<16, 4, 32>(buf0, 8192, d_B1pk + e * 65536, 32768, r16base, warpN * 4, lane, acc);
    // epilogue: h1 = tanh; o += h1.W2; dh1 = W2*(1-h1^2) -> packed into buf1 (psA=8192)
    #pragma unroll
    for (int mf = 0; mf < 2; mf++) {
        int r0 = warpM * 32 + mf * 16 + gg, r1 = r0 + 8;
        float orow0 = 0.0f, orow1 = 0.0f;
        #pragma unroll
        for (int nf = 0; nf < 4; nf++) {
            int n0 = warpN * 32 + nf * 8 + 2 * tIG;
            float2 w2v = *(const float2*)&W2g[e * HID + n0];
            float t0 = tanhf(acc[mf][nf][0]), t1 = tanhf(acc[mf][nf][1]);
            float t2 = tanhf(acc[mf][nf][2]), t3 = tanhf(acc[mf][nf][3]);
            orow0 += t0 * w2v.x + t1 * w2v.y;
            orow1 += t2 * w2v.x + t3 * w2v.y;
            float d0 = w2v.x * (1.0f - t0 * t0), d1 = w2v.y * (1.0f - t1 * t1);
            float d2 = w2v.x * (1.0f - t2 * t2), d3 = w2v.y * (1.0f - t3 * t3);
            uint32_t hi, lo;
            split2(d0, d1, hi, lo);
            int i0 = apk_idx(r0, n0); buf1[i0] = hi; buf1[8192 + i0] = lo;
            split2(d2, d3, hi, lo);
            int i1 = apk_idx(r1, n0); buf1[i1] = hi; buf1[8192 + i1] = lo;
        }
        atomicAdd(&o_s[r0], orow0);
        atomicAdd(&o_s[r1], orow1);
    }
    __syncthreads();

    // energy: atomic segment-sum over images
    if (tid < na)
        atomicAdd(&out_energy[image_idx[aidx[tid]]], o_s[tid] + b2g[e]);

    // ================= B1: t = dh1 @ W1^T; dh0 = (1-h0^2)*t =================
    #pragma unroll
    for (int mf = 0; mf < 2; mf++)
        #pragma unroll
        for (int nf = 0; nf < 4; nf++)
            #pragma unroll
            for (int q = 0; q < 4; q++) acc[mf][nf][q] = 0.0f;
    gemm_phase<16, 4, 32>(buf1, 8192, d_BT1pk + e * 65536, 32768, r16base, warpN * 4, lane, acc);
    #pragma unroll
    for (int mf = 0; mf < 2; mf++) {
        int r0 = warpM * 32 + mf * 16 + gg, r1 = r0 + 8;
        #pragma unroll
        for (int nf = 0; nf < 4; nf++) {
            int n0 = warpN * 32 + nf * 8 + 2 * tIG;
            int i0 = apk_idx(r0, n0), i1 = apk_idx(r1, n0);
            float2 h0a = unsplit2(buf0[i0], buf0[8192 + i0]);
            float2 h0b = unsplit2(buf0[i1], buf0[8192 + i1]);
            float v0 = (1.0f - h0a.x * h0a.x) * acc[mf][nf][0];
            float v1 = (1.0f - h0a.y * h0a.y) * acc[mf][nf][1];
            float v2 = (1.0f - h0b.x * h0b.x) * acc[mf][nf][2];
            float v3 = (1.0f - h0b.y * h0b.y) * acc[mf][nf][3];
            uint32_t hi, lo;
            split2(v0, v1, hi, lo); buf0[i0] = hi; buf0[8192 + i0] = lo;
            split2(v2, v3, hi, lo); buf0[i1] = hi; buf0[8192 + i1] = lo;
        }
    }
    __syncthreads();

    // ================= B0: g = dh0 @ W0^T -> d_g =================
    #pragma unroll
    for (int mf = 0; mf < 2; mf++)
        #pragma unroll
        for (int nf = 0; nf < 4; nf++)
            #pragma unroll
            for (int q = 0; q < 4; q++) acc[mf][nf][q] = 0.0f;
    gemm_phase<16, 2, 16>(buf0, 8192, d_BT0pk + e * 32768, 16384, r16base, warpN * 2, lane, acc);
    #pragma unroll
    for (int mf = 0; mf < 2; mf++) {
        int r0 = warpM * 32 + mf * 16 + gg, r1 = r0 + 8;
        #pragma unroll
        for (int nf = 0; nf < 2; nf++) {
            int n0 = warpN * 16 + nf * 8 + 2 * tIG;
            if (r0 < na)
                *(float2*)&d_g[(size_t)aidx[r0] * IN_DIM + n0] =
                    make_float2(acc[mf][nf][0], acc[mf][nf][1]);
            if (r1 < na)
                *(float2*)&d_g[(size_t)aidx[r1] * IN_DIM + n0] =
                    make_float2(acc[mf][nf][2], acc[mf][nf][3]);
        }
    }
}

// ---------------- sparse force scatter: forces = -fprimes^T @ g ----------------
__global__ void force_kernel(const int* __restrict__ rows,
                             const int* __restrict__ cols,
                             const float* __restrict__ vals,
                             int nnz, float* __restrict__ forces) {
    const int4*   r4 = (const int4*)rows;
    const int4*   c4 = (const int4*)cols;
    const float4* v4 = (const float4*)vals;
    const int nnz4 = nnz >> 2;
    int i = blockIdx.x * blockDim.x + threadIdx.x;
    int stride = gridDim.x * blockDim.x;
    for (; i < nnz4; i += stride) {
        int4 r = __ldg(&r4[i]);
        int4 c = __ldg(&c4[i]);
        float4 v = __ldg(&v4[i]);
        atomicAdd(&forces[c.x], -v.x * d_g[r.x]);
        atomicAdd(&forces[c.y], -v.y * d_g[r.y]);
        atomicAdd(&forces[c.z], -v.z * d_g[r.z]);
        atomicAdd(&forces[c.w], -v.w * d_g[r.w]);
    }
    int tail = nnz & 3;
    if (tail && blockIdx.x == 0 && threadIdx.x < tail) {
        int k = (nnz & ~3) + threadIdx.x;
        atomicAdd(&forces[cols[k]], -vals[k] * d_g[rows[k]]);
    }
}

// ---------------- launch ----------------
extern "C" void kernel_launch(void* const* d_in, const int* in_sizes, int n_in,
                              void* d_out, int out_size) {
    const float* fingerprints = (const float*)d_in[0];
    const int*   atomic_num   = (const int*)  d_in[1];
    const int*   image_idx    = (const int*)  d_in[2];
    const int*   fprime_rows  = (const int*)  d_in[3];
    const int*   fprime_cols  = (const int*)  d_in[4];
    const float* fprime_vals  = (const float*)d_in[5];
    const float* W0 = (const float*)d_in[6];
    const float* b0 = (const float*)d_in[7];
    const float* W1 = (const float*)d_in[8];
    const float* b1 = (const float*)d_in[9];
    const float* W2 = (const float*)d_in[10];
    const float* b2 = (const float*)d_in[11];
    float* out = (float*)d_out;                 // [0,500): energy, [500,150500): forces
    const int nnz = in_sizes[3];

    zero_kernel<<<(out_size + 255) / 256, 256>>>(out, out_size);

    count_kernel<<<1, 1024>>>(atomic_num, N_ATOMS);
    scatter_kernel<<<(N_ATOMS + 255) / 256, 256>>>(atomic_num, N_ATOMS);

    // split + fragment-pack weights (1,441,792 u32 outputs)
    prep_kernel<<<(1441792 + 255) / 256, 256>>>(W0, W1);

    // fused tensor-core MLP fwd+bwd
    const int smem_bytes = (32768 + M_BLK + M_BLK) * 4;   // 131,584 B
    cudaFuncSetAttribute(mlp_mma_kernel, cudaFuncAttributeMaxDynamicSharedMemorySize, 136 * 1024);
    dim3 grid((N_ATOMS + M_BLK - 1) / M_BLK, N_ELEM);
    mlp_mma_kernel<<<grid, MLP_THREADS, smem_bytes>>>(
        fingerprints, image_idx, b0, b1, W2, b2, out);

    // sparse force accumulation (vectorized x4)
    force_kernel<<<4096, 256>>>(fprime_rows, fprime_cols, fprime_vals, nnz, out + N_IMG);
}